// round 15
// baseline (speedup 1.0000x reference)
#include <cuda_runtime.h>
#include <cuda_fp16.h>
#include <stdint.h>
#include <math.h>

#define B_WIN   1024
#define NTOK    64
#define DIMC    512
#define NH      16
#define HD      32
#define M_TOT   (B_WIN * NTOK)           /* 65536 */
#define SCALE_F 0.17677669529663687f     /* 32^-0.5 */
#define L2E_F   1.4426950408889634f
#define QSCALE  (SCALE_F * L2E_F)        /* q pre-scale incl. log2(e) fold */

/* ---------------- static device scratch (no allocation) ------------------ */
__device__ uint32_t g_bias_h2[NH * NTOK * 32];      /* fp16x2 pairs, xL2E */
__device__ __half g_x[(size_t)M_TOT * DIMC];
__device__ __half g_att[(size_t)M_TOT * DIMC];      /* [b*64+tok][h*32+d] */
__device__ __half g_wq[3 * DIMC * DIMC];
__device__ __half g_wp[DIMC * DIMC];
/* q/k/v fp16, layout [b][h][tok][d]; q scaled by SCALE*L2E */
__device__ __half g_q[(size_t)M_TOT * DIMC];
__device__ __half g_k[(size_t)M_TOT * DIMC];
__device__ __half g_v[(size_t)M_TOT * DIMC];

/* ---------------- portable tensor-core helpers (sm_80+) ------------------ */
__device__ __forceinline__ uint32_t smem_u32(const void* p) {
    return (uint32_t)__cvta_generic_to_shared(p);
}
__device__ __forceinline__ void ldsm4(uint32_t* r, uint32_t addr) {
    asm volatile("ldmatrix.sync.aligned.m8n8.x4.shared.b16 {%0,%1,%2,%3}, [%4];"
        : "=r"(r[0]), "=r"(r[1]), "=r"(r[2]), "=r"(r[3]) : "r"(addr));
}
__device__ __forceinline__ void ldsm4t(uint32_t* r, uint32_t addr) {
    asm volatile("ldmatrix.sync.aligned.m8n8.x4.trans.shared.b16 {%0,%1,%2,%3}, [%4];"
        : "=r"(r[0]), "=r"(r[1]), "=r"(r[2]), "=r"(r[3]) : "r"(addr));
}
__device__ __forceinline__ void mma_f16(float* d, const uint32_t* a, const uint32_t* b) {
    asm volatile("mma.sync.aligned.m16n8k16.row.col.f32.f16.f16.f32 "
        "{%0,%1,%2,%3}, {%4,%5,%6,%7}, {%8,%9}, {%0,%1,%2,%3};"
        : "+f"(d[0]), "+f"(d[1]), "+f"(d[2]), "+f"(d[3])
        : "r"(a[0]), "r"(a[1]), "r"(a[2]), "r"(a[3]), "r"(b[0]), "r"(b[1]));
}
#define CP_ASYNC16(dst, src) \
    asm volatile("cp.async.cg.shared.global [%0], [%1], 16;" :: "r"(dst), "l"(src))
#define CP_COMMIT()  asm volatile("cp.async.commit_group;" ::: "memory")
#define CP_WAIT1()   asm volatile("cp.async.wait_group 1;" ::: "memory")
#define CP_WAIT0()   asm volatile("cp.async.wait_group 0;" ::: "memory")

__device__ __forceinline__ uint32_t pack_h2(float a, float b) {
    __half2 h = __floats2half2_rn(a, b);
    return *(uint32_t*)&h;
}
__device__ __forceinline__ uint32_t ex2_h2(uint32_t t) {
    uint32_t r;
    asm("ex2.approx.f16x2 %0, %1;" : "=r"(r) : "r"(t));
    return r;
}
__device__ __forceinline__ uint32_t hadd2_u(uint32_t a, uint32_t b) {
    __half2 t = __hadd2(*(__half2*)&a, *(__half2*)&b);
    return *(uint32_t*)&t;
}

/* ================= fused prep: converts + bias table ===================== */
__global__ void prep_kernel(const float* __restrict__ x,
                            const float* __restrict__ qkv_w,
                            const float* __restrict__ proj_w,
                            const float* __restrict__ theta_max,
                            const float* __restrict__ a_p, const float* __restrict__ b_p,
                            const float* __restrict__ a_r, const float* __restrict__ b_r)
{
    const int blk = blockIdx.x;
    if (blk < 33792) {
        const float* src;
        __half* dst;
        int i;
        if (blk < 32768)      { src = x;      dst = g_x;  i = blk * 256 + threadIdx.x; }
        else if (blk < 33536) { src = qkv_w;  dst = g_wq; i = (blk - 32768) * 256 + threadIdx.x; }
        else                  { src = proj_w; dst = g_wp; i = (blk - 33536) * 256 + threadIdx.x; }
        float4 v = ((const float4*)src)[i];
        ((uint2*)dst)[i] = make_uint2(pack_h2(v.x, v.y), pack_h2(v.z, v.w));
    } else {
        int i = (blk - 33792) * 256 + threadIdx.x;      /* pair index < 32768 */
        int h = i >> 11;
        int rem = i & 2047;
        int row = rem >> 5, j2 = rem & 31;
        float bv2[2];
#pragma unroll
        for (int t = 0; t < 2; ++t) {
            int j = j2 * 2 + t;
            int dr = (row >> 3) - (j >> 3);
            int dc = (row & 7) - (j & 7);
            int idx_r  = ((dr % 15) + 15) % 15;
            int idx_az = ((dc % 15) + 15) % 15;
            float az = (float)dc * (2.0f * 3.14159265358979323846f / 32.0f);
            float ra = (float)dr * (theta_max[0] / 32.0f);
            bv2[t] = (a_p[idx_az * NH + h] * cosf(az) + b_p[idx_az * NH + h] * sinf(az)
                    + a_r[idx_r  * NH + h] * cosf(ra) + b_r[idx_r  * NH + h] * sinf(ra)) * L2E_F;
        }
        g_bias_h2[i] = pack_h2(bv2[0], bv2[1]);
    }
}

/* ================= mma.sync fp16 GEMM (K64 chunks, 3-stage ring) ========= */
/* CTA tile 128x128, 16 warps (4m x 4n), warp tile 32x32, 512 threads.      */
/* Stage 32KB = A 128x64 fp16 | B 128x64 fp16. 8 chunks, 8 barriers.        */
#define STAGE_B 32768
#define SMEM_TOTAL (3 * STAGE_B)

template<int MODE>
__global__ __launch_bounds__(512, 2) void mma_gemm(const float* __restrict__ bias,
                                                   float* __restrict__ out)
{
    extern __shared__ char smem[];
    const uint32_t sb = smem_u32(smem);
    const int tid = threadIdx.x, wid = tid >> 5, lane = tid & 31;
    const int m0 = blockIdx.y << 7;
    const int n0 = blockIdx.x << 7;
    const int wm = (wid & 3) << 5;          /* warp row offset 0..96 */
    const int wn = (wid >> 2) << 5;         /* warp col offset 0..96 */

    const __half* __restrict__ A = (MODE == 0) ? g_x : g_att;
    const __half* __restrict__ W = (MODE == 0) ? g_wq : g_wp;

    float acc[2][4][4];
#pragma unroll
    for (int a = 0; a < 2; a++)
#pragma unroll
        for (int b = 0; b < 4; b++)
#pragma unroll
            for (int c = 0; c < 4; c++) acc[a][b][c] = 0.0f;

    /* loader: 512 threads; each loads 2 16B-chunks per operand per K64 chunk.
       row r = tid>>2 (0..127); slots s = (tid&3) and (tid&3)+4; s -> (ksl, half). */
    const int c_r  = tid >> 2, q0 = tid & 3;
    const int ksl_a = q0 >> 1,        half_a = q0 & 1;          /* slot q0   */
    const int ksl_b = (q0 + 4) >> 1,  half_b = q0 & 1;          /* slot q0+4 */
    const int xr = (c_r >> 2) & 1;
    const uint32_t offa = 16u * (ksl_a * 256 + c_r * 2 + (half_a ^ xr));
    const uint32_t offb = 16u * (ksl_b * 256 + c_r * 2 + (half_b ^ xr));
    const int kca = ksl_a * 16 + half_a * 8;
    const int kcb = ksl_b * 16 + half_b * 8;
    const __half* Arow = A + (size_t)(m0 + c_r) * DIMC;
    const __half* Wrow = W + (size_t)(n0 + c_r) * DIMC;

#define ISSUE(ch) do {                                                         \
    const uint32_t stg = sb + ((ch) % 3) * STAGE_B;                            \
    const int kk = (ch) << 6;                                                  \
    CP_ASYNC16(stg + offa,         Arow + kk + kca);                           \
    CP_ASYNC16(stg + offb,         Arow + kk + kcb);                           \
    CP_ASYNC16(stg + 16384 + offa, Wrow + kk + kca);                           \
    CP_ASYNC16(stg + 16384 + offb, Wrow + kk + kcb);                           \
    CP_COMMIT();                                                               \
} while (0)

    ISSUE(0); ISSUE(1);
    const int rloc = lane & 15, hsel = lane >> 4;
    const uint32_t aoff0 = 16u * ((wm +  0 + rloc) * 2 + (hsel ^ (((wm +  0 + rloc) >> 2) & 1)));
    const uint32_t aoff1 = 16u * ((wm + 16 + rloc) * 2 + (hsel ^ (((wm + 16 + rloc) >> 2) & 1)));
    const uint32_t boff0 = 16u * ((wn +  0 + rloc) * 2 + (hsel ^ (((wn +  0 + rloc) >> 2) & 1)));
    const uint32_t boff1 = 16u * ((wn + 16 + rloc) * 2 + (hsel ^ (((wn + 16 + rloc) >> 2) & 1)));

    for (int ch = 0; ch < 8; ++ch) {
        if (ch <= 5) CP_WAIT1();
        else         CP_WAIT0();
        __syncthreads();
        if (ch + 2 < 8) ISSUE(ch + 2);
        const uint32_t stg = sb + (ch % 3) * STAGE_B;
#pragma unroll
        for (int ks = 0; ks < 4; ++ks) {
            const uint32_t ko = (uint32_t)(ks * 4096);
            uint32_t ah[2][4], bh[2][4];
            ldsm4(ah[0], stg + ko + aoff0);
            ldsm4(ah[1], stg + ko + aoff1);
            ldsm4(bh[0], stg + 16384 + ko + boff0);
            ldsm4(bh[1], stg + 16384 + ko + boff1);
#pragma unroll
            for (int bt = 0; bt < 2; ++bt) {
#pragma unroll
                for (int nf = 0; nf < 2; ++nf) {
                    uint32_t bb[2] = {bh[bt][nf], bh[bt][nf + 2]};
#pragma unroll
                    for (int mt = 0; mt < 2; ++mt)
                        mma_f16(acc[mt][bt * 2 + nf], ah[mt], bb);
                }
            }
        }
    }
#undef ISSUE

    /* ---- epilogue ---- */
#pragma unroll
    for (int mt = 0; mt < 2; ++mt) {
#pragma unroll
        for (int f = 0; f < 4; ++f) {
            const int n = n0 + wn + (f >> 1) * 16 + (f & 1) * 8 + (lane & 3) * 2;
            const float2 bv = *(const float2*)&bias[n];
#pragma unroll
            for (int hrow = 0; hrow < 2; ++hrow) {
                const int m = m0 + wm + mt * 16 + (lane >> 2) + hrow * 8;
                float vx = acc[mt][f][hrow * 2 + 0] + bv.x;
                float vy = acc[mt][f][hrow * 2 + 1] + bv.y;
                if (MODE == 0) {
                    const int sel = n >> 9;
                    const int h = (n >> 5) & 15, d = n & 31;
                    if (sel == 0) { vx *= QSCALE; vy *= QSCALE; }
                    __half* dst = (sel == 0) ? g_q : ((sel == 1) ? g_k : g_v);
                    size_t base = (((size_t)(m >> 6) * NH + h) * NTOK + (m & 63)) * HD + d;
                    *(uint32_t*)&dst[base] = pack_h2(vx, vy);
                } else {
                    *(float2*)&out[(size_t)m * DIMC + n] = make_float2(vx, vy);
                }
            }
        }
    }
}

/* ================= tensor-core attention (fp16, f16x2 exp, no-max) ====== */
#define PITCH 80

__global__ __launch_bounds__(256, 2) void attn_mma_kernel()
{
    const int cta = blockIdx.x;           /* 0 .. 8191 */
    const int b = cta >> 3, hp = cta & 7;
    const int tid = threadIdx.x, wid = tid >> 5, lane = tid & 31;
    const int h2 = wid >> 2;
    const int h  = hp * 2 + h2;
    const int m0 = (wid & 3) << 4;

    __shared__ __align__(16) unsigned char qbuf[2][64 * PITCH];
    __shared__ __align__(16) unsigned char kbuf[2][64 * PITCH];
    __shared__ __align__(16) unsigned char vbuf[2][64 * PITCH];

    /* stage q,k,v for both heads: 1536 x 16B chunks, 6 per thread */
    {
        const size_t base0 = ((size_t)b * NH + hp * 2) * (NTOK * HD);
#pragma unroll
        for (int it = 0; it < 6; ++it) {
            int e = tid + it * 256;
            int which = e / 512;
            int e2 = e & 511;
            int hh = e2 >> 8;
            int e3 = e2 & 255;
            int r = e3 >> 2, c = e3 & 3;
            const __half* gsrc = (which == 0) ? g_q : ((which == 1) ? g_k : g_v);
            unsigned char* dbuf = (which == 0) ? &qbuf[hh][0]
                                : ((which == 1) ? &kbuf[hh][0] : &vbuf[hh][0]);
            CP_ASYNC16(smem_u32(dbuf + r * PITCH + c * 16),
                       gsrc + base0 + (size_t)hh * (NTOK * HD) + r * HD + c * 8);
        }
        CP_COMMIT();
        CP_WAIT0();
    }
    __syncthreads();

    const uint32_t qb = smem_u32(&qbuf[h2][0]);
    const uint32_t kb = smem_u32(&kbuf[h2][0]);
    const uint32_t vb = smem_u32(&vbuf[h2][0]);

    const int rA = m0 + (lane >> 2);      /* local token row (frag row) */
    const int cp = (lane & 3) << 1;       /* fragment col pair */

    /* q A-frags via ldsm4: rows m0..m0+15, 2 k-tiles over d=32 */
    uint32_t aq[2][4];
    {
        const int arow = m0 + (lane & 7) + ((lane >> 3) & 1) * 8;
        const uint32_t acol = (lane >> 4) * 16;
#pragma unroll
        for (int kt = 0; kt < 2; ++kt)
            ldsm4(aq[kt], qb + (uint32_t)arow * PITCH + kt * 32 + acol);
    }

    /* S = q k^T (already in log2 domain) */
    float sc[8][4];
#pragma unroll
    for (int nt = 0; nt < 8; ++nt) { sc[nt][0] = sc[nt][1] = sc[nt][2] = sc[nt][3] = 0.0f; }
    {
        const int brow_l = lane & 15;
        const uint32_t bcol = (lane >> 4) * 16;
#pragma unroll
        for (int g = 0; g < 4; ++g) {
            const uint32_t roff = (uint32_t)(g * 16 + brow_l) * PITCH;
#pragma unroll
            for (int kt = 0; kt < 2; ++kt) {
                uint32_t bt[4];
                ldsm4(bt, kb + roff + kt * 32 + bcol);
                uint32_t b0[2] = {bt[0], bt[2]}, b1[2] = {bt[1], bt[3]};
                mma_f16(sc[2 * g],     aq[kt], b0);
                mma_f16(sc[2 * g + 1], aq[kt], b1);
            }
        }
    }

    /* bias (fp16x2, pre-scaled by L2E) added in h2; exp = ex2; deferred norm */
    const uint32_t* bh2 = g_bias_h2 + (h << 11);
    const int bcolp = (cp >> 1);             /* pair column base */
    uint32_t pe[8][2];
    float sA = 0.0f, sB = 0.0f;
#pragma unroll
    for (int nt = 0; nt < 8; ++nt) {
        uint32_t bA = bh2[rA * 32 + nt * 4 + bcolp];
        uint32_t bB = bh2[(rA + 8) * 32 + nt * 4 + bcolp];
        pe[nt][0] = ex2_h2(hadd2_u(pack_h2(sc[nt][0], sc[nt][1]), bA));
        pe[nt][1] = ex2_h2(hadd2_u(pack_h2(sc[nt][2], sc[nt][3]), bB));
        float2 fA = __half22float2(*(__half2*)&pe[nt][0]);
        float2 fB = __half22float2(*(__half2*)&pe[nt][1]);
        sA += fA.x + fA.y;
        sB += fB.x + fB.y;
    }
    sA += __shfl_xor_sync(0xffffffffu, sA, 1);
    sA += __shfl_xor_sync(0xffffffffu, sA, 2);
    sB += __shfl_xor_sync(0xffffffffu, sB, 1);
    sB += __shfl_xor_sync(0xffffffffu, sB, 2);
    const float iA = 1.0f / sA, iB = 1.0f / sB;

    /* O = P V (unnormalized), V via ldmatrix.trans */
    float oc[4][4];
#pragma unroll
    for (int nt = 0; nt < 4; ++nt) { oc[nt][0] = oc[nt][1] = oc[nt][2] = oc[nt][3] = 0.0f; }
    const uint32_t lrow = (lane & 7) + ((lane >> 3) & 1) * 8;
    const uint32_t lcol16 = (lane >> 4);
#pragma unroll
    for (int kt = 0; kt < 4; ++kt) {
        uint32_t pa[4] = {pe[2 * kt][0], pe[2 * kt][1],
                          pe[2 * kt + 1][0], pe[2 * kt + 1][1]};
        uint32_t v0[4], v1[4];
        const uint32_t roff = (uint32_t)((kt * 16 + lrow) * PITCH);
        ldsm4t(v0, vb + roff + lcol16 * 16);
        ldsm4t(v1, vb + roff + (lcol16 + 2) * 16);
        uint32_t bv[4][2] = {{v0[0], v0[1]}, {v0[2], v0[3]},
                             {v1[0], v1[1]}, {v1[2], v1[3]}};
#pragma unroll
        for (int nt = 0; nt < 4; ++nt)
            mma_f16(oc[nt], pa, bv[nt]);
    }

    /* epilogue: normalize rows and write fp16 to g_att */
    const size_t obA = ((size_t)(b * NTOK + rA)) * DIMC + h * HD;
    const size_t obB = obA + (size_t)8 * DIMC;
#pragma unroll
    for (int nt = 0; nt < 4; ++nt) {
        const int d = nt * 8 + cp;
        *(uint32_t*)&g_att[obA + d] = pack_h2(oc[nt][0] * iA, oc[nt][1] * iA);
        *(uint32_t*)&g_att[obB + d] = pack_h2(oc[nt][2] * iB, oc[nt][3] * iB);
    }
}

/* ========================================================================= */
extern "C" void kernel_launch(void* const* d_in, const int* in_sizes, int n_in,
                              void* d_out, int out_size)
{
    (void)in_sizes; (void)n_in; (void)out_size;
    const float* x      = (const float*)d_in[0];
    const float* theta  = (const float*)d_in[1];
    const float* qkv_w  = (const float*)d_in[2];
    const float* qkv_b  = (const float*)d_in[3];
    const float* proj_w = (const float*)d_in[4];
    const float* proj_b = (const float*)d_in[5];
    const float* a_p    = (const float*)d_in[6];
    const float* b_p    = (const float*)d_in[7];
    const float* a_r    = (const float*)d_in[8];
    const float* b_r    = (const float*)d_in[9];
    float* out = (float*)d_out;

    static int smem_set = 0;
    if (!smem_set) {
        cudaFuncSetAttribute(mma_gemm<0>, cudaFuncAttributeMaxDynamicSharedMemorySize, SMEM_TOTAL);
        cudaFuncSetAttribute(mma_gemm<1>, cudaFuncAttributeMaxDynamicSharedMemorySize, SMEM_TOTAL);
        smem_set = 1;
    }

    prep_kernel<<<33920, 256>>>(x, qkv_w, proj_w, theta, a_p, b_p, a_r, b_r);
    mma_gemm<0><<<dim3(12, 512), 512, SMEM_TOTAL>>>(qkv_b, nullptr);
    attn_mma_kernel<<<B_WIN * 8, 256>>>();
    mma_gemm<1><<<dim3(4, 512), 512, SMEM_TOTAL>>>(proj_b, out);
}

// round 16
// speedup vs baseline: 1.0568x; 1.0568x over previous
#include <cuda_runtime.h>
#include <cuda_fp16.h>
#include <stdint.h>
#include <math.h>

#define B_WIN   1024
#define NTOK    64
#define DIMC    512
#define NH      16
#define HD      32
#define M_TOT   (B_WIN * NTOK)           /* 65536 */
#define SCALE_F 0.17677669529663687f     /* 32^-0.5 */
#define L2E_F   1.4426950408889634f
#define QSCALE  (SCALE_F * L2E_F)        /* q pre-scale incl. log2(e) fold */

/* ---------------- static device scratch (no allocation) ------------------ */
__device__ uint32_t g_bias_h2[NH * NTOK * 32];      /* fp16x2 pairs, xL2E */
__device__ __half g_x[(size_t)M_TOT * DIMC];
__device__ __half g_att[(size_t)M_TOT * DIMC];      /* [b*64+tok][h*32+d] */
__device__ __half g_wq[3 * DIMC * DIMC];
__device__ __half g_wp[DIMC * DIMC];
/* q/k/v fp16, layout [b][h][tok][d]; q scaled by SCALE*L2E */
__device__ __half g_q[(size_t)M_TOT * DIMC];
__device__ __half g_k[(size_t)M_TOT * DIMC];
__device__ __half g_v[(size_t)M_TOT * DIMC];

/* ---------------- portable tensor-core helpers (sm_80+) ------------------ */
__device__ __forceinline__ uint32_t smem_u32(const void* p) {
    return (uint32_t)__cvta_generic_to_shared(p);
}
__device__ __forceinline__ void ldsm4(uint32_t* r, uint32_t addr) {
    asm volatile("ldmatrix.sync.aligned.m8n8.x4.shared.b16 {%0,%1,%2,%3}, [%4];"
        : "=r"(r[0]), "=r"(r[1]), "=r"(r[2]), "=r"(r[3]) : "r"(addr));
}
__device__ __forceinline__ void ldsm4t(uint32_t* r, uint32_t addr) {
    asm volatile("ldmatrix.sync.aligned.m8n8.x4.trans.shared.b16 {%0,%1,%2,%3}, [%4];"
        : "=r"(r[0]), "=r"(r[1]), "=r"(r[2]), "=r"(r[3]) : "r"(addr));
}
__device__ __forceinline__ void mma_f16(float* d, const uint32_t* a, const uint32_t* b) {
    asm volatile("mma.sync.aligned.m16n8k16.row.col.f32.f16.f16.f32 "
        "{%0,%1,%2,%3}, {%4,%5,%6,%7}, {%8,%9}, {%0,%1,%2,%3};"
        : "+f"(d[0]), "+f"(d[1]), "+f"(d[2]), "+f"(d[3])
        : "r"(a[0]), "r"(a[1]), "r"(a[2]), "r"(a[3]), "r"(b[0]), "r"(b[1]));
}
#define CP_ASYNC16(dst, src) \
    asm volatile("cp.async.cg.shared.global [%0], [%1], 16;" :: "r"(dst), "l"(src))
#define CP_COMMIT()  asm volatile("cp.async.commit_group;" ::: "memory")
#define CP_WAIT2()   asm volatile("cp.async.wait_group 2;" ::: "memory")
#define CP_WAIT1()   asm volatile("cp.async.wait_group 1;" ::: "memory")
#define CP_WAIT0()   asm volatile("cp.async.wait_group 0;" ::: "memory")

__device__ __forceinline__ uint32_t pack_h2(float a, float b) {
    __half2 h = __floats2half2_rn(a, b);
    return *(uint32_t*)&h;
}
__device__ __forceinline__ uint32_t ex2_h2(uint32_t t) {
    uint32_t r;
    asm("ex2.approx.f16x2 %0, %1;" : "=r"(r) : "r"(t));
    return r;
}
__device__ __forceinline__ uint32_t hadd2_u(uint32_t a, uint32_t b) {
    __half2 t = __hadd2(*(__half2*)&a, *(__half2*)&b);
    return *(uint32_t*)&t;
}

/* ================= fused prep: converts + bias table ===================== */
__global__ void prep_kernel(const float* __restrict__ x,
                            const float* __restrict__ qkv_w,
                            const float* __restrict__ proj_w,
                            const float* __restrict__ theta_max,
                            const float* __restrict__ a_p, const float* __restrict__ b_p,
                            const float* __restrict__ a_r, const float* __restrict__ b_r)
{
    const int blk = blockIdx.x;
    if (blk < 33792) {
        const float* src;
        __half* dst;
        int i;
        if (blk < 32768)      { src = x;      dst = g_x;  i = blk * 256 + threadIdx.x; }
        else if (blk < 33536) { src = qkv_w;  dst = g_wq; i = (blk - 32768) * 256 + threadIdx.x; }
        else                  { src = proj_w; dst = g_wp; i = (blk - 33536) * 256 + threadIdx.x; }
        float4 v = ((const float4*)src)[i];
        ((uint2*)dst)[i] = make_uint2(pack_h2(v.x, v.y), pack_h2(v.z, v.w));
    } else {
        int i = (blk - 33792) * 256 + threadIdx.x;      /* pair index < 32768 */
        int h = i >> 11;
        int rem = i & 2047;
        int row = rem >> 5, j2 = rem & 31;
        float bv2[2];
#pragma unroll
        for (int t = 0; t < 2; ++t) {
            int j = j2 * 2 + t;
            int dr = (row >> 3) - (j >> 3);
            int dc = (row & 7) - (j & 7);
            int idx_r  = ((dr % 15) + 15) % 15;
            int idx_az = ((dc % 15) + 15) % 15;
            float az = (float)dc * (2.0f * 3.14159265358979323846f / 32.0f);
            float ra = (float)dr * (theta_max[0] / 32.0f);
            bv2[t] = (a_p[idx_az * NH + h] * cosf(az) + b_p[idx_az * NH + h] * sinf(az)
                    + a_r[idx_r  * NH + h] * cosf(ra) + b_r[idx_r  * NH + h] * sinf(ra)) * L2E_F;
        }
        g_bias_h2[i] = pack_h2(bv2[0], bv2[1]);
    }
}

/* ================= mma.sync fp16 GEMM (R14 config + full unroll) ========= */
/* CTA tile 128x128, 16 warps (4m x 4n), warp tile 32x32, 512 thr, 4-stage. */
#define STAGE_B 16384
#define SMEM_TOTAL (4 * STAGE_B)

template<int MODE>
__global__ __launch_bounds__(512, 2) void mma_gemm(const float* __restrict__ bias,
                                                   float* __restrict__ out)
{
    extern __shared__ char smem[];
    const uint32_t sb = smem_u32(smem);
    const int tid = threadIdx.x, wid = tid >> 5, lane = tid & 31;
    const int m0 = blockIdx.y << 7;
    const int n0 = blockIdx.x << 7;
    const int wm = (wid & 3) << 5;          /* warp row offset 0..96 */
    const int wn = (wid >> 2) << 5;         /* warp col offset 0..96 */

    const __half* __restrict__ A = (MODE == 0) ? g_x : g_att;
    const __half* __restrict__ W = (MODE == 0) ? g_wq : g_wp;

    float acc[2][4][4];
#pragma unroll
    for (int a = 0; a < 2; a++)
#pragma unroll
        for (int b = 0; b < 4; b++)
#pragma unroll
            for (int c = 0; c < 4; c++) acc[a][b][c] = 0.0f;

    /* loader: 512 threads, one 16B chunk per operand each */
    const int c_r0 = tid >> 2, c_q0 = tid & 3;
    const int ksl0 = c_q0 >> 1, half0 = c_q0 & 1;
    const uint32_t off0 = 16u * (ksl0 * 256 + c_r0 * 2 + (half0 ^ ((c_r0 >> 2) & 1)));
    const int kc0 = ksl0 * 16 + half0 * 8;
    const __half* Arow = A + (size_t)(m0 + c_r0) * DIMC + kc0;
    const __half* Wrow = W + (size_t)(n0 + c_r0) * DIMC + kc0;

#define ISSUE(ch) do {                                                         \
    const uint32_t stg = sb + ((ch) & 3) * STAGE_B;                            \
    CP_ASYNC16(stg + off0,        Arow + ((ch) << 5));                         \
    CP_ASYNC16(stg + 8192 + off0, Wrow + ((ch) << 5));                         \
    CP_COMMIT();                                                               \
} while (0)

    ISSUE(0); ISSUE(1); ISSUE(2);
    const int rloc = lane & 15, hsel = lane >> 4;
    const uint32_t aoff0 = 16u * ((wm +  0 + rloc) * 2 + (hsel ^ (((wm +  0 + rloc) >> 2) & 1)));
    const uint32_t aoff1 = 16u * ((wm + 16 + rloc) * 2 + (hsel ^ (((wm + 16 + rloc) >> 2) & 1)));
    const uint32_t boff0 = 16u * ((wn +  0 + rloc) * 2 + (hsel ^ (((wn +  0 + rloc) >> 2) & 1)));
    const uint32_t boff1 = 16u * ((wn + 16 + rloc) * 2 + (hsel ^ (((wn + 16 + rloc) >> 2) & 1)));

#pragma unroll
    for (int ch = 0; ch < 16; ++ch) {
        if (ch <= 13)      CP_WAIT2();
        else if (ch == 14) CP_WAIT1();
        else               CP_WAIT0();
        __syncthreads();
        if (ch + 3 < 16) ISSUE(ch + 3);
        const uint32_t stg = sb + (ch & 3) * STAGE_B;
#pragma unroll
        for (int ks = 0; ks < 2; ++ks) {
            const uint32_t ko = (uint32_t)(ks * 256 * 16);
            uint32_t ah[2][4], bh[2][4];
            ldsm4(ah[0], stg + ko + aoff0);
            ldsm4(ah[1], stg + ko + aoff1);
            ldsm4(bh[0], stg + 8192 + ko + boff0);
            ldsm4(bh[1], stg + 8192 + ko + boff1);
#pragma unroll
            for (int bt = 0; bt < 2; ++bt) {
#pragma unroll
                for (int nf = 0; nf < 2; ++nf) {
                    uint32_t bb[2] = {bh[bt][nf], bh[bt][nf + 2]};
#pragma unroll
                    for (int mt = 0; mt < 2; ++mt)
                        mma_f16(acc[mt][bt * 2 + nf], ah[mt], bb);
                }
            }
        }
    }
#undef ISSUE

    /* ---- epilogue ---- */
#pragma unroll
    for (int mt = 0; mt < 2; ++mt) {
#pragma unroll
        for (int f = 0; f < 4; ++f) {
            const int n = n0 + wn + (f >> 1) * 16 + (f & 1) * 8 + (lane & 3) * 2;
            const float2 bv = *(const float2*)&bias[n];
#pragma unroll
            for (int hrow = 0; hrow < 2; ++hrow) {
                const int m = m0 + wm + mt * 16 + (lane >> 2) + hrow * 8;
                float vx = acc[mt][f][hrow * 2 + 0] + bv.x;
                float vy = acc[mt][f][hrow * 2 + 1] + bv.y;
                if (MODE == 0) {
                    const int sel = n >> 9;
                    const int h = (n >> 5) & 15, d = n & 31;
                    if (sel == 0) { vx *= QSCALE; vy *= QSCALE; }
                    __half* dst = (sel == 0) ? g_q : ((sel == 1) ? g_k : g_v);
                    size_t base = (((size_t)(m >> 6) * NH + h) * NTOK + (m & 63)) * HD + d;
                    *(uint32_t*)&dst[base] = pack_h2(vx, vy);
                } else {
                    *(float2*)&out[(size_t)m * DIMC + n] = make_float2(vx, vy);
                }
            }
        }
    }
}

/* ================= tensor-core attention (fp16, f16x2 exp, no-max) ====== */
#define PITCH 80

__global__ __launch_bounds__(256, 2) void attn_mma_kernel()
{
    const int cta = blockIdx.x;           /* 0 .. 8191 */
    const int b = cta >> 3, hp = cta & 7;
    const int tid = threadIdx.x, wid = tid >> 5, lane = tid & 31;
    const int h2 = wid >> 2;
    const int h  = hp * 2 + h2;
    const int m0 = (wid & 3) << 4;

    __shared__ __align__(16) unsigned char qbuf[2][64 * PITCH];
    __shared__ __align__(16) unsigned char kbuf[2][64 * PITCH];
    __shared__ __align__(16) unsigned char vbuf[2][64 * PITCH];

    /* stage q,k,v for both heads: 1536 x 16B chunks, 6 per thread */
    {
        const size_t base0 = ((size_t)b * NH + hp * 2) * (NTOK * HD);
#pragma unroll
        for (int it = 0; it < 6; ++it) {
            int e = tid + it * 256;
            int which = e / 512;
            int e2 = e & 511;
            int hh = e2 >> 8;
            int e3 = e2 & 255;
            int r = e3 >> 2, c = e3 & 3;
            const __half* gsrc = (which == 0) ? g_q : ((which == 1) ? g_k : g_v);
            unsigned char* dbuf = (which == 0) ? &qbuf[hh][0]
                                : ((which == 1) ? &kbuf[hh][0] : &vbuf[hh][0]);
            CP_ASYNC16(smem_u32(dbuf + r * PITCH + c * 16),
                       gsrc + base0 + (size_t)hh * (NTOK * HD) + r * HD + c * 8);
        }
        CP_COMMIT();
        CP_WAIT0();
    }
    __syncthreads();

    const uint32_t qb = smem_u32(&qbuf[h2][0]);
    const uint32_t kb = smem_u32(&kbuf[h2][0]);
    const uint32_t vb = smem_u32(&vbuf[h2][0]);

    const int rA = m0 + (lane >> 2);      /* local token row (frag row) */
    const int cp = (lane & 3) << 1;       /* fragment col pair */

    /* q A-frags via ldsm4: rows m0..m0+15, 2 k-tiles over d=32 */
    uint32_t aq[2][4];
    {
        const int arow = m0 + (lane & 7) + ((lane >> 3) & 1) * 8;
        const uint32_t acol = (lane >> 4) * 16;
#pragma unroll
        for (int kt = 0; kt < 2; ++kt)
            ldsm4(aq[kt], qb + (uint32_t)arow * PITCH + kt * 32 + acol);
    }

    /* S = q k^T (already in log2 domain) */
    float sc[8][4];
#pragma unroll
    for (int nt = 0; nt < 8; ++nt) { sc[nt][0] = sc[nt][1] = sc[nt][2] = sc[nt][3] = 0.0f; }
    {
        const int brow_l = lane & 15;
        const uint32_t bcol = (lane >> 4) * 16;
#pragma unroll
        for (int g = 0; g < 4; ++g) {
            const uint32_t roff = (uint32_t)(g * 16 + brow_l) * PITCH;
#pragma unroll
            for (int kt = 0; kt < 2; ++kt) {
                uint32_t bt[4];
                ldsm4(bt, kb + roff + kt * 32 + bcol);
                uint32_t b0[2] = {bt[0], bt[2]}, b1[2] = {bt[1], bt[3]};
                mma_f16(sc[2 * g],     aq[kt], b0);
                mma_f16(sc[2 * g + 1], aq[kt], b1);
            }
        }
    }

    /* bias (fp16x2, pre-scaled by L2E) added in h2; exp = ex2; deferred norm */
    const uint32_t* bh2 = g_bias_h2 + (h << 11);
    const int bcolp = (cp >> 1);             /* pair column base */
    uint32_t pe[8][2];
    float sA = 0.0f, sB = 0.0f;
#pragma unroll
    for (int nt = 0; nt < 8; ++nt) {
        uint32_t bA = bh2[rA * 32 + nt * 4 + bcolp];
        uint32_t bB = bh2[(rA + 8) * 32 + nt * 4 + bcolp];
        pe[nt][0] = ex2_h2(hadd2_u(pack_h2(sc[nt][0], sc[nt][1]), bA));
        pe[nt][1] = ex2_h2(hadd2_u(pack_h2(sc[nt][2], sc[nt][3]), bB));
        float2 fA = __half22float2(*(__half2*)&pe[nt][0]);
        float2 fB = __half22float2(*(__half2*)&pe[nt][1]);
        sA += fA.x + fA.y;
        sB += fB.x + fB.y;
    }
    sA += __shfl_xor_sync(0xffffffffu, sA, 1);
    sA += __shfl_xor_sync(0xffffffffu, sA, 2);
    sB += __shfl_xor_sync(0xffffffffu, sB, 1);
    sB += __shfl_xor_sync(0xffffffffu, sB, 2);
    const float iA = 1.0f / sA, iB = 1.0f / sB;

    /* O = P V (unnormalized), V via ldmatrix.trans */
    float oc[4][4];
#pragma unroll
    for (int nt = 0; nt < 4; ++nt) { oc[nt][0] = oc[nt][1] = oc[nt][2] = oc[nt][3] = 0.0f; }
    const uint32_t lrow = (lane & 7) + ((lane >> 3) & 1) * 8;
    const uint32_t lcol16 = (lane >> 4);
#pragma unroll
    for (int kt = 0; kt < 4; ++kt) {
        uint32_t pa[4] = {pe[2 * kt][0], pe[2 * kt][1],
                          pe[2 * kt + 1][0], pe[2 * kt + 1][1]};
        uint32_t v0[4], v1[4];
        const uint32_t roff = (uint32_t)((kt * 16 + lrow) * PITCH);
        ldsm4t(v0, vb + roff + lcol16 * 16);
        ldsm4t(v1, vb + roff + (lcol16 + 2) * 16);
        uint32_t bv[4][2] = {{v0[0], v0[1]}, {v0[2], v0[3]},
                             {v1[0], v1[1]}, {v1[2], v1[3]}};
#pragma unroll
        for (int nt = 0; nt < 4; ++nt)
            mma_f16(oc[nt], pa, bv[nt]);
    }

    /* epilogue: normalize rows and write fp16 to g_att */
    const size_t obA = ((size_t)(b * NTOK + rA)) * DIMC + h * HD;
    const size_t obB = obA + (size_t)8 * DIMC;
#pragma unroll
    for (int nt = 0; nt < 4; ++nt) {
        const int d = nt * 8 + cp;
        *(uint32_t*)&g_att[obA + d] = pack_h2(oc[nt][0] * iA, oc[nt][1] * iA);
        *(uint32_t*)&g_att[obB + d] = pack_h2(oc[nt][2] * iB, oc[nt][3] * iB);
    }
}

/* ========================================================================= */
extern "C" void kernel_launch(void* const* d_in, const int* in_sizes, int n_in,
                              void* d_out, int out_size)
{
    (void)in_sizes; (void)n_in; (void)out_size;
    const float* x      = (const float*)d_in[0];
    const float* theta  = (const float*)d_in[1];
    const float* qkv_w  = (const float*)d_in[2];
    const float* qkv_b  = (const float*)d_in[3];
    const float* proj_w = (const float*)d_in[4];
    const float* proj_b = (const float*)d_in[5];
    const float* a_p    = (const float*)d_in[6];
    const float* b_p    = (const float*)d_in[7];
    const float* a_r    = (const float*)d_in[8];
    const float* b_r    = (const float*)d_in[9];
    float* out = (float*)d_out;

    static int smem_set = 0;
    if (!smem_set) {
        cudaFuncSetAttribute(mma_gemm<0>, cudaFuncAttributeMaxDynamicSharedMemorySize, SMEM_TOTAL);
        cudaFuncSetAttribute(mma_gemm<1>, cudaFuncAttributeMaxDynamicSharedMemorySize, SMEM_TOTAL);
        smem_set = 1;
    }

    prep_kernel<<<33920, 256>>>(x, qkv_w, proj_w, theta, a_p, b_p, a_r, b_r);
    mma_gemm<0><<<dim3(12, 512), 512, SMEM_TOTAL>>>(qkv_b, nullptr);
    attn_mma_kernel<<<B_WIN * 8, 256>>>();
    mma_gemm<1><<<dim3(4, 512), 512, SMEM_TOTAL>>>(proj_b, out);
}